// round 13
// baseline (speedup 1.0000x reference)
#include <cuda_runtime.h>
#include <cuda_bf16.h>
#include <math.h>
#include <stdint.h>

// ContrastiveHead NT-Xent. Symmetric sim: upper-triangular 128x128 tiles.
// CTA = (row panel bi, <=8 bj tiles). 256 threads (8 warps, 4m x 2n),
// TWO CTAs per SM (fp8 34KB tiles make the smem fit) -> scheduler overlaps
// one CTA's epilogue with the other's GEMM. FP8 e4m3 mma, b16-view frags.

#define NROWS 8192
#define HALFN 4096
#define DIM   256
#define BM    128
#define KP    136                    // row stride in b16 units (272 B)
#define NTILE 64
#define TSLICE 8
#define NCTAS 288
#define NTHREADS 256
#define TILE_B16 (BM * KP)
#define SMEM_BYTES (3 * TILE_B16 * 2)   // 104448 B -> 2 CTAs/SM

__device__ uint8_t g_f8[NROWS * DIM];
__device__ float g_pos[NROWS];
__device__ float g_sumexp[NROWS];

// ---------------------------------------------------------------------------
__device__ __forceinline__ uint32_t fp8x4(float v0, float v1, float v2, float v3) {
    uint32_t r;
    asm("{\n\t.reg .b16 lo, hi;\n\t"
        "cvt.rn.satfinite.e4m3x2.f32 lo, %2, %1;\n\t"
        "cvt.rn.satfinite.e4m3x2.f32 hi, %4, %3;\n\t"
        "mov.b32 %0, {lo, hi};\n\t}"
        : "=r"(r) : "f"(v0), "f"(v1), "f"(v2), "f"(v3));
    return r;
}

__global__ void normpos_kernel(const float* __restrict__ q,
                               const float* __restrict__ k,
                               float* __restrict__ out) {
    int gt = blockIdx.x * blockDim.x + threadIdx.x;
    if (gt == 0) out[0] = 0.0f;
    if (gt < NROWS) g_sumexp[gt] = 0.0f;
    int gw   = gt >> 5;
    int lane = gt & 31;
    if (gw >= HALFN) return;

    const float4* q4 = (const float4*)(q + (size_t)gw * DIM);
    const float4* k4 = (const float4*)(k + (size_t)gw * DIM);
    float4 a0 = q4[lane*2], a1 = q4[lane*2+1];
    float4 b0 = k4[lane*2], b1 = k4[lane*2+1];
    float sq = a0.x*a0.x + a0.y*a0.y + a0.z*a0.z + a0.w*a0.w
             + a1.x*a1.x + a1.y*a1.y + a1.z*a1.z + a1.w*a1.w;
    float sk = b0.x*b0.x + b0.y*b0.y + b0.z*b0.z + b0.w*b0.w
             + b1.x*b1.x + b1.y*b1.y + b1.z*b1.z + b1.w*b1.w;
    float dp = a0.x*b0.x + a0.y*b0.y + a0.z*b0.z + a0.w*b0.w
             + a1.x*b1.x + a1.y*b1.y + a1.z*b1.z + a1.w*b1.w;
    #pragma unroll
    for (int o = 16; o; o >>= 1) {
        sq += __shfl_xor_sync(0xffffffffu, sq, o);
        sk += __shfl_xor_sync(0xffffffffu, sk, o);
        dp += __shfl_xor_sync(0xffffffffu, dp, o);
    }
    float nq = fmaxf(sqrtf(sq), 1e-12f);
    float nk = fmaxf(sqrtf(sk), 1e-12f);
    float sclq = 1.0f / nq;
    float sclk = 1.0f / nk;

    if (lane == 0) {
        float p = dp / (nq * nk);
        g_pos[gw]         = p;
        g_pos[gw + HALFN] = p;
    }

    uint2 oq;
    oq.x = fp8x4(a0.x * sclq, a0.y * sclq, a0.z * sclq, a0.w * sclq);
    oq.y = fp8x4(a1.x * sclq, a1.y * sclq, a1.z * sclq, a1.w * sclq);
    *(uint2*)(g_f8 + (size_t)gw * DIM + lane * 8) = oq;

    uint2 ok;
    ok.x = fp8x4(b0.x * sclk, b0.y * sclk, b0.z * sclk, b0.w * sclk);
    ok.y = fp8x4(b1.x * sclk, b1.y * sclk, b1.z * sclk, b1.w * sclk);
    *(uint2*)(g_f8 + (size_t)(gw + HALFN) * DIM + lane * 8) = ok;
}

// ---------------------------------------------------------------------------
__device__ __forceinline__ void ldsm_x4(uint32_t* r, const void* p) {
    uint32_t a = (uint32_t)__cvta_generic_to_shared(p);
    asm volatile("ldmatrix.sync.aligned.m8n8.x4.shared.b16 {%0,%1,%2,%3}, [%4];"
                 : "=r"(r[0]), "=r"(r[1]), "=r"(r[2]), "=r"(r[3]) : "r"(a));
}
__device__ __forceinline__ void qmma(float* c, const uint32_t* a, const uint32_t* b) {
    asm volatile(
        "mma.sync.aligned.m16n8k32.row.col.f32.e4m3.e4m3.f32 "
        "{%0,%1,%2,%3}, {%4,%5,%6,%7}, {%8,%9}, {%0,%1,%2,%3};"
        : "+f"(c[0]), "+f"(c[1]), "+f"(c[2]), "+f"(c[3])
        : "r"(a[0]), "r"(a[1]), "r"(a[2]), "r"(a[3]), "r"(b[0]), "r"(b[1]));
}
__device__ __forceinline__ float ex2(float x) {
    float y; asm("ex2.approx.ftz.f32 %0, %1;" : "=f"(y) : "f"(x)); return y;
}
__device__ __forceinline__ void cp16(void* smem_dst, const void* gsrc) {
    uint32_t d = (uint32_t)__cvta_generic_to_shared(smem_dst);
    asm volatile("cp.async.cg.shared.global [%0], [%1], 16;" :: "r"(d), "l"(gsrc));
}
__device__ __forceinline__ void cp_commit() { asm volatile("cp.async.commit_group;"); }
__device__ __forceinline__ void cp_wait0()  { asm volatile("cp.async.wait_group 0;"); }

// Tile fill: 128 rows x 256 B = 2048 x 16B chunks; 8 per thread.
__device__ __forceinline__ void load_tile(__nv_bfloat16* dst, int row0, int tid) {
    #pragma unroll
    for (int i = 0; i < 8; ++i) {
        int idx = tid + i * NTHREADS;
        int r = idx >> 4, c = idx & 15;
        cp16(dst + r * KP + c * 8, g_f8 + (size_t)(row0 + r) * DIM + c * 16);
    }
}

// ---------------------------------------------------------------------------
// Fused symmetric GEMM + exp. 256 threads = 8 warps (4m x 2n).
// Per warp: 2 m-tiles (m16) x 8 n-tiles (n8); fp8 k32 mma, 8 k-steps.
// ---------------------------------------------------------------------------
__global__ void __launch_bounds__(NTHREADS, 2) sim_kernel() {
    extern __shared__ __nv_bfloat16 sm[];
    __nv_bfloat16* As = sm;
    __nv_bfloat16* Bbuf[2] = { sm + TILE_B16, sm + 2 * TILE_B16 };

    int tid = threadIdx.x;
    int lane = tid & 31;
    int w = tid >> 5;
    int wm = w >> 1;            // 0..3
    int wn = w & 1;             // 0..1

    int rem = blockIdx.x;
    int bi = 0;
    for (;;) {
        int s = (NTILE - bi + TSLICE - 1) / TSLICE;
        if (rem < s) break;
        rem -= s; ++bi;
    }
    int bj0 = bi + rem * TSLICE;
    int ntl = NTILE - bj0; if (ntl > TSLICE) ntl = TSLICE;

    load_tile(As, bi * BM, tid);
    load_tile(Bbuf[0], bj0 * BM, tid);
    cp_commit();

    // ldmatrix addressing (b16 view of fp8 data).
    int al = lane & 15;
    int acolo = (lane >> 4) * 8;
    int brow2 = ((lane >> 4) & 1) * 8 + (lane & 7);
    int bcol2 = ((lane >> 3) & 1) * 8;
    int g  = lane >> 2;
    int qd = (lane & 3) * 2;
    const float C10 = 14.426950408889634f;   // 10 * log2(e)

    float rowsum[4] = {0.f, 0.f, 0.f, 0.f};

    for (int t = 0; t < ntl; ++t) {
        cp_wait0();
        __syncthreads();

        if (t + 1 < ntl) load_tile(Bbuf[(t + 1) & 1], (bj0 + t + 1) * BM, tid);
        cp_commit();

        const __nv_bfloat16* Bs = Bbuf[t & 1];
        int bj = bj0 + t;
        bool diag = (bj == bi);

        float cfr[2][8][4];
        #pragma unroll
        for (int mt = 0; mt < 2; ++mt)
            #pragma unroll
            for (int nt = 0; nt < 8; ++nt)
                #pragma unroll
                for (int e = 0; e < 4; ++e) cfr[mt][nt][e] = 0.f;

        #pragma unroll
        for (int kk = 0; kk < 8; ++kk) {
            int k0 = kk * 16;                 // 16 b16 = 32 fp8 per step
            uint32_t afr[2][4], bfr[4][4];
            #pragma unroll
            for (int mt = 0; mt < 2; ++mt)
                ldsm_x4(afr[mt], As + (wm * 32 + mt * 16 + al) * KP + k0 + acolo);
            #pragma unroll
            for (int p = 0; p < 4; ++p)
                ldsm_x4(bfr[p], Bs + (wn * 64 + p * 16 + brow2) * KP + k0 + bcol2);
            #pragma unroll
            for (int mt = 0; mt < 2; ++mt)
                #pragma unroll
                for (int nt = 0; nt < 8; ++nt)
                    qmma(cfr[mt][nt], afr[mt], &bfr[nt >> 1][(nt & 1) * 2]);
        }

        float colsum[8][2];
        #pragma unroll
        for (int nt = 0; nt < 8; ++nt) { colsum[nt][0] = 0.f; colsum[nt][1] = 0.f; }

        if (!diag) {
            #pragma unroll
            for (int mt = 0; mt < 2; ++mt) {
                #pragma unroll
                for (int nt = 0; nt < 8; ++nt) {
                    float* cc = cfr[mt][nt];
                    float e0 = ex2(fmaf(cc[0], C10, -C10));
                    float e1 = ex2(fmaf(cc[1], C10, -C10));
                    float e2 = ex2(fmaf(cc[2], C10, -C10));
                    float e3 = ex2(fmaf(cc[3], C10, -C10));
                    rowsum[mt * 2 + 0] += e0 + e1;
                    rowsum[mt * 2 + 1] += e2 + e3;
                    colsum[nt][0] += e0 + e2;
                    colsum[nt][1] += e1 + e3;
                }
            }
            #pragma unroll
            for (int nt = 0; nt < 8; ++nt) {
                float c0 = colsum[nt][0], c1 = colsum[nt][1];
                #pragma unroll
                for (int o = 4; o <= 16; o <<= 1) {
                    c0 += __shfl_xor_sync(0xffffffffu, c0, o);
                    c1 += __shfl_xor_sync(0xffffffffu, c1, o);
                }
                if (lane < 4) {
                    int col = bj * BM + wn * 64 + nt * 8 + lane * 2;
                    atomicAdd(&g_sumexp[col],     c0);
                    atomicAdd(&g_sumexp[col + 1], c1);
                }
            }
        } else {
            #pragma unroll
            for (int mt = 0; mt < 2; ++mt) {
                int r0 = wm * 32 + mt * 16 + g;
                #pragma unroll
                for (int nt = 0; nt < 8; ++nt) {
                    int c0i = wn * 64 + nt * 8 + qd;
                    float* cc = cfr[mt][nt];
                    float e0 = (c0i     != r0    ) ? ex2(fmaf(cc[0], C10, -C10)) : 0.f;
                    float e1 = (c0i + 1 != r0    ) ? ex2(fmaf(cc[1], C10, -C10)) : 0.f;
                    float e2 = (c0i     != r0 + 8) ? ex2(fmaf(cc[2], C10, -C10)) : 0.f;
                    float e3 = (c0i + 1 != r0 + 8) ? ex2(fmaf(cc[3], C10, -C10)) : 0.f;
                    rowsum[mt * 2 + 0] += e0 + e1;
                    rowsum[mt * 2 + 1] += e2 + e3;
                }
            }
        }
    }

    // Flush row sums.
    #pragma unroll
    for (int j = 0; j < 4; ++j) {
        rowsum[j] += __shfl_xor_sync(0xffffffffu, rowsum[j], 1);
        rowsum[j] += __shfl_xor_sync(0xffffffffu, rowsum[j], 2);
    }
    if ((lane & 3) == 0) {
        #pragma unroll
        for (int mt = 0; mt < 2; ++mt) {
            int r0 = bi * BM + wm * 32 + mt * 16 + g;
            atomicAdd(&g_sumexp[r0],     rowsum[mt * 2 + 0]);
            atomicAdd(&g_sumexp[r0 + 8], rowsum[mt * 2 + 1]);
        }
    }
}

// ---------------------------------------------------------------------------
__global__ void finalize_kernel(float* __restrict__ out) {
    int i = blockIdx.x * blockDim.x + threadIdx.x;
    float v = (10.f + __logf(g_sumexp[i]) - 10.f * g_pos[i]) * (1.0f / (float)NROWS);
    #pragma unroll
    for (int o = 16; o; o >>= 1) v += __shfl_xor_sync(0xffffffffu, v, o);
    if ((threadIdx.x & 31) == 0) atomicAdd(out, v);
}

extern "C" void kernel_launch(void* const* d_in, const int* in_sizes, int n_in,
                              void* d_out, int out_size) {
    const float* q = (const float*)d_in[0];
    const float* k = (const float*)d_in[1];
    float* out = (float*)d_out;

    cudaFuncSetAttribute(sim_kernel, cudaFuncAttributeMaxDynamicSharedMemorySize,
                         SMEM_BYTES);

    normpos_kernel<<<(HALFN * 32) / 256, 256>>>(q, k, out);
    sim_kernel<<<NCTAS, NTHREADS, SMEM_BYTES>>>();
    finalize_kernel<<<NROWS / 512, 512>>>(out);
}

// round 14
// speedup vs baseline: 1.4946x; 1.4946x over previous
#include <cuda_runtime.h>
#include <cuda_bf16.h>
#include <math.h>
#include <stdint.h>

// ContrastiveHead NT-Xent. Symmetric sim: upper-triangular 128x128 tiles.
// CTA = (row panel bi, <=8 bj tiles). 256 threads (8 warps, 4m x 2n),
// TWO CTAs per SM (fp8 34KB tiles). Register-slimmed epilogue (no colsum
// array) to stay under the 128-reg cap of launch_bounds(256,2) w/o spills.

#define NROWS 8192
#define HALFN 4096
#define DIM   256
#define BM    128
#define KP    136                    // row stride in b16 units (272 B)
#define NTILE 64
#define TSLICE 8
#define NCTAS 288
#define NTHREADS 256
#define TILE_B16 (BM * KP)
#define SMEM_BYTES (3 * TILE_B16 * 2)   // 104448 B -> 2 CTAs/SM

__device__ uint8_t g_f8[NROWS * DIM];
__device__ float g_pos[NROWS];
__device__ float g_sumexp[NROWS];

// ---------------------------------------------------------------------------
__device__ __forceinline__ uint32_t fp8x4(float v0, float v1, float v2, float v3) {
    uint32_t r;
    asm("{\n\t.reg .b16 lo, hi;\n\t"
        "cvt.rn.satfinite.e4m3x2.f32 lo, %2, %1;\n\t"
        "cvt.rn.satfinite.e4m3x2.f32 hi, %4, %3;\n\t"
        "mov.b32 %0, {lo, hi};\n\t}"
        : "=r"(r) : "f"(v0), "f"(v1), "f"(v2), "f"(v3));
    return r;
}

__global__ void normpos_kernel(const float* __restrict__ q,
                               const float* __restrict__ k,
                               float* __restrict__ out) {
    int gt = blockIdx.x * blockDim.x + threadIdx.x;
    if (gt == 0) out[0] = 0.0f;
    if (gt < NROWS) g_sumexp[gt] = 0.0f;
    int gw   = gt >> 5;
    int lane = gt & 31;
    if (gw >= HALFN) return;

    const float4* q4 = (const float4*)(q + (size_t)gw * DIM);
    const float4* k4 = (const float4*)(k + (size_t)gw * DIM);
    float4 a0 = q4[lane*2], a1 = q4[lane*2+1];
    float4 b0 = k4[lane*2], b1 = k4[lane*2+1];
    float sq = a0.x*a0.x + a0.y*a0.y + a0.z*a0.z + a0.w*a0.w
             + a1.x*a1.x + a1.y*a1.y + a1.z*a1.z + a1.w*a1.w;
    float sk = b0.x*b0.x + b0.y*b0.y + b0.z*b0.z + b0.w*b0.w
             + b1.x*b1.x + b1.y*b1.y + b1.z*b1.z + b1.w*b1.w;
    float dp = a0.x*b0.x + a0.y*b0.y + a0.z*b0.z + a0.w*b0.w
             + a1.x*b1.x + a1.y*b1.y + a1.z*b1.z + a1.w*b1.w;
    #pragma unroll
    for (int o = 16; o; o >>= 1) {
        sq += __shfl_xor_sync(0xffffffffu, sq, o);
        sk += __shfl_xor_sync(0xffffffffu, sk, o);
        dp += __shfl_xor_sync(0xffffffffu, dp, o);
    }
    float nq = fmaxf(sqrtf(sq), 1e-12f);
    float nk = fmaxf(sqrtf(sk), 1e-12f);
    float sclq = 1.0f / nq;
    float sclk = 1.0f / nk;

    if (lane == 0) {
        float p = dp / (nq * nk);
        g_pos[gw]         = p;
        g_pos[gw + HALFN] = p;
    }

    uint2 oq;
    oq.x = fp8x4(a0.x * sclq, a0.y * sclq, a0.z * sclq, a0.w * sclq);
    oq.y = fp8x4(a1.x * sclq, a1.y * sclq, a1.z * sclq, a1.w * sclq);
    *(uint2*)(g_f8 + (size_t)gw * DIM + lane * 8) = oq;

    uint2 ok;
    ok.x = fp8x4(b0.x * sclk, b0.y * sclk, b0.z * sclk, b0.w * sclk);
    ok.y = fp8x4(b1.x * sclk, b1.y * sclk, b1.z * sclk, b1.w * sclk);
    *(uint2*)(g_f8 + (size_t)(gw + HALFN) * DIM + lane * 8) = ok;
}

// ---------------------------------------------------------------------------
__device__ __forceinline__ void ldsm_x4(uint32_t* r, const void* p) {
    uint32_t a = (uint32_t)__cvta_generic_to_shared(p);
    asm volatile("ldmatrix.sync.aligned.m8n8.x4.shared.b16 {%0,%1,%2,%3}, [%4];"
                 : "=r"(r[0]), "=r"(r[1]), "=r"(r[2]), "=r"(r[3]) : "r"(a));
}
__device__ __forceinline__ void qmma(float* c, const uint32_t* a, const uint32_t* b) {
    asm volatile(
        "mma.sync.aligned.m16n8k32.row.col.f32.e4m3.e4m3.f32 "
        "{%0,%1,%2,%3}, {%4,%5,%6,%7}, {%8,%9}, {%0,%1,%2,%3};"
        : "+f"(c[0]), "+f"(c[1]), "+f"(c[2]), "+f"(c[3])
        : "r"(a[0]), "r"(a[1]), "r"(a[2]), "r"(a[3]), "r"(b[0]), "r"(b[1]));
}
__device__ __forceinline__ float ex2(float x) {
    float y; asm("ex2.approx.ftz.f32 %0, %1;" : "=f"(y) : "f"(x)); return y;
}
__device__ __forceinline__ void cp16(void* smem_dst, const void* gsrc) {
    uint32_t d = (uint32_t)__cvta_generic_to_shared(smem_dst);
    asm volatile("cp.async.cg.shared.global [%0], [%1], 16;" :: "r"(d), "l"(gsrc));
}
__device__ __forceinline__ void cp_commit() { asm volatile("cp.async.commit_group;"); }
__device__ __forceinline__ void cp_wait0()  { asm volatile("cp.async.wait_group 0;"); }

// Tile fill: 128 rows x 256 B = 2048 x 16B chunks; 8 per thread.
__device__ __forceinline__ void load_tile(__nv_bfloat16* dst, int row0, int tid) {
    #pragma unroll
    for (int i = 0; i < 8; ++i) {
        int idx = tid + i * NTHREADS;
        int r = idx >> 4, c = idx & 15;
        cp16(dst + r * KP + c * 8, g_f8 + (size_t)(row0 + r) * DIM + c * 16);
    }
}

// ---------------------------------------------------------------------------
// Fused symmetric GEMM + exp. 256 threads = 8 warps (4m x 2n).
// Per warp: 2 m-tiles (m16) x 8 n-tiles (n8); fp8 k32 mma, 8 k-steps.
// ---------------------------------------------------------------------------
__global__ void __launch_bounds__(NTHREADS, 2) sim_kernel() {
    extern __shared__ __nv_bfloat16 sm[];
    __nv_bfloat16* As = sm;
    __nv_bfloat16* Bbuf[2] = { sm + TILE_B16, sm + 2 * TILE_B16 };

    int tid = threadIdx.x;
    int lane = tid & 31;
    int w = tid >> 5;
    int wm = w >> 1;            // 0..3
    int wn = w & 1;             // 0..1

    int rem = blockIdx.x;
    int bi = 0;
    for (;;) {
        int s = (NTILE - bi + TSLICE - 1) / TSLICE;
        if (rem < s) break;
        rem -= s; ++bi;
    }
    int bj0 = bi + rem * TSLICE;
    int ntl = NTILE - bj0; if (ntl > TSLICE) ntl = TSLICE;

    load_tile(As, bi * BM, tid);
    load_tile(Bbuf[0], bj0 * BM, tid);
    cp_commit();

    // ldmatrix addressing (b16 view of fp8 data).
    int al = lane & 15;
    int acolo = (lane >> 4) * 8;
    int brow2 = ((lane >> 4) & 1) * 8 + (lane & 7);
    int bcol2 = ((lane >> 3) & 1) * 8;
    int g  = lane >> 2;
    int qd = (lane & 3) * 2;
    const float C10 = 14.426950408889634f;   // 10 * log2(e)

    float rowsum[4] = {0.f, 0.f, 0.f, 0.f};

    for (int t = 0; t < ntl; ++t) {
        cp_wait0();
        __syncthreads();

        if (t + 1 < ntl) load_tile(Bbuf[(t + 1) & 1], (bj0 + t + 1) * BM, tid);
        cp_commit();

        const __nv_bfloat16* Bs = Bbuf[t & 1];
        int bj = bj0 + t;
        bool diag = (bj == bi);

        float cfr[2][8][4];
        #pragma unroll
        for (int mt = 0; mt < 2; ++mt)
            #pragma unroll
            for (int nt = 0; nt < 8; ++nt)
                #pragma unroll
                for (int e = 0; e < 4; ++e) cfr[mt][nt][e] = 0.f;

        #pragma unroll
        for (int kk = 0; kk < 8; ++kk) {
            int k0 = kk * 16;                 // 16 b16 = 32 fp8 per step
            uint32_t afr[2][4], bfr[4][4];
            #pragma unroll
            for (int mt = 0; mt < 2; ++mt)
                ldsm_x4(afr[mt], As + (wm * 32 + mt * 16 + al) * KP + k0 + acolo);
            #pragma unroll
            for (int p = 0; p < 4; ++p)
                ldsm_x4(bfr[p], Bs + (wn * 64 + p * 16 + brow2) * KP + k0 + bcol2);
            #pragma unroll
            for (int mt = 0; mt < 2; ++mt)
                #pragma unroll
                for (int nt = 0; nt < 8; ++nt)
                    qmma(cfr[mt][nt], afr[mt], &bfr[nt >> 1][(nt & 1) * 2]);
        }

        // Register-slim epilogue: nt-outer, column sums in 2 scalars flushed
        // immediately (no colsum array -> no spills at launch_bounds(256,2)).
        if (!diag) {
            #pragma unroll
            for (int nt = 0; nt < 8; ++nt) {
                float c0 = 0.f, c1 = 0.f;
                #pragma unroll
                for (int mt = 0; mt < 2; ++mt) {
                    float* cc = cfr[mt][nt];
                    float e0 = ex2(fmaf(cc[0], C10, -C10));
                    float e1 = ex2(fmaf(cc[1], C10, -C10));
                    float e2 = ex2(fmaf(cc[2], C10, -C10));
                    float e3 = ex2(fmaf(cc[3], C10, -C10));
                    rowsum[mt * 2 + 0] += e0 + e1;
                    rowsum[mt * 2 + 1] += e2 + e3;
                    c0 += e0 + e2;
                    c1 += e1 + e3;
                }
                #pragma unroll
                for (int o = 4; o <= 16; o <<= 1) {
                    c0 += __shfl_xor_sync(0xffffffffu, c0, o);
                    c1 += __shfl_xor_sync(0xffffffffu, c1, o);
                }
                if (lane < 4) {
                    int col = bj * BM + wn * 64 + nt * 8 + lane * 2;
                    atomicAdd(&g_sumexp[col],     c0);
                    atomicAdd(&g_sumexp[col + 1], c1);
                }
            }
        } else {
            #pragma unroll
            for (int nt = 0; nt < 8; ++nt) {
                int c0i = wn * 64 + nt * 8 + qd;
                #pragma unroll
                for (int mt = 0; mt < 2; ++mt) {
                    int r0 = wm * 32 + mt * 16 + g;
                    float* cc = cfr[mt][nt];
                    float e0 = (c0i     != r0    ) ? ex2(fmaf(cc[0], C10, -C10)) : 0.f;
                    float e1 = (c0i + 1 != r0    ) ? ex2(fmaf(cc[1], C10, -C10)) : 0.f;
                    float e2 = (c0i     != r0 + 8) ? ex2(fmaf(cc[2], C10, -C10)) : 0.f;
                    float e3 = (c0i + 1 != r0 + 8) ? ex2(fmaf(cc[3], C10, -C10)) : 0.f;
                    rowsum[mt * 2 + 0] += e0 + e1;
                    rowsum[mt * 2 + 1] += e2 + e3;
                }
            }
        }
    }

    // Flush row sums.
    #pragma unroll
    for (int j = 0; j < 4; ++j) {
        rowsum[j] += __shfl_xor_sync(0xffffffffu, rowsum[j], 1);
        rowsum[j] += __shfl_xor_sync(0xffffffffu, rowsum[j], 2);
    }
    if ((lane & 3) == 0) {
        #pragma unroll
        for (int mt = 0; mt < 2; ++mt) {
            int r0 = bi * BM + wm * 32 + mt * 16 + g;
            atomicAdd(&g_sumexp[r0],     rowsum[mt * 2 + 0]);
            atomicAdd(&g_sumexp[r0 + 8], rowsum[mt * 2 + 1]);
        }
    }
}

// ---------------------------------------------------------------------------
__global__ void finalize_kernel(float* __restrict__ out) {
    int i = blockIdx.x * blockDim.x + threadIdx.x;
    float v = (10.f + __logf(g_sumexp[i]) - 10.f * g_pos[i]) * (1.0f / (float)NROWS);
    #pragma unroll
    for (int o = 16; o; o >>= 1) v += __shfl_xor_sync(0xffffffffu, v, o);
    if ((threadIdx.x & 31) == 0) atomicAdd(out, v);
}

extern "C" void kernel_launch(void* const* d_in, const int* in_sizes, int n_in,
                              void* d_out, int out_size) {
    const float* q = (const float*)d_in[0];
    const float* k = (const float*)d_in[1];
    float* out = (float*)d_out;

    cudaFuncSetAttribute(sim_kernel, cudaFuncAttributeMaxDynamicSharedMemorySize,
                         SMEM_BYTES);

    normpos_kernel<<<(HALFN * 32) / 256, 256>>>(q, k, out);
    sim_kernel<<<NCTAS, NTHREADS, SMEM_BYTES>>>();
    finalize_kernel<<<NROWS / 512, 512>>>(out);
}